// round 15
// baseline (speedup 1.0000x reference)
#include <cuda_runtime.h>
#include <cuda_bf16.h>
#include <math.h>
#include <stdint.h>

#define N_NODES 50000
#define N_EDGES 800000
#define VOCAB 15000
#define IN_FEATS 128
#define HIDDEN 32
#define HEADS 4
#define FEAT 128           // HEADS*HIDDEN
#define N_GRAPHS 64
#define NEG_SLOPE 0.2f
#define BCAP 64            // bucket capacity per node (P(deg>=64) ~ 1e-20 for Poisson(16))

// ---------------- scratch (static device globals; no allocation) ----------------
// feat tables stored HEAD-INTERLEAVED: row[d*4 + h] = feat[h*32 + d]
__device__ __align__(16) float g_V[(size_t)VOCAB * FEAT];      // vocab-level layer-0 feat (interleaved)
__device__ __align__(16) float g_elv[VOCAB * HEADS];
__device__ __align__(16) float g_erv[VOCAB * HEADS];
__device__ __align__(16) float g_feat[(size_t)N_NODES * FEAT]; // layer-1 feat (interleaved)
__device__ __align__(16) float g_h[(size_t)N_NODES * FEAT];    // layer output (standard layout)
__device__ __align__(16) float g_el[N_NODES * HEADS];
__device__ __align__(16) float g_er[N_NODES * HEADS];
__device__ __align__(16) int   g_cur[N_NODES];                 // fill count; reset by agg1 (and static-init)
__device__ __align__(16) int   g_bn[(size_t)N_NODES * BCAP];   // bucket: src node ids
__device__ __align__(16) int   g_bw[(size_t)N_NODES * BCAP];   // bucket: word_ids[src]
__device__ __align__(16) float4 g_bp[(size_t)N_NODES * BCAP];  // bucket: attention exp per edge (4 heads)
__device__ unsigned g_pool[N_GRAPHS * FEAT];                   // armed by agg1 (and static zero = valid identity)

// TF32 rounding (matches JAX/XLA default f32 matmul precision on GPU)
__device__ __forceinline__ float tf32r(float x) {
    unsigned u;
    asm("cvt.rna.tf32.f32 %0, %1;" : "=r"(u) : "f"(x));
    return __uint_as_float(u);
}
// exact split: bf16_hi + bf16_lo == tf32(x)
__device__ __forceinline__ void split_bf(float x, __nv_bfloat16& h, __nv_bfloat16& l) {
    float xt = tf32r(x);
    h = __float2bfloat16(xt);
    l = __float2bfloat16(xt - __bfloat162float(h));
}

// order-preserving float <-> uint encode for atomicMax
__device__ __forceinline__ unsigned fenc(float f) {
    unsigned u = __float_as_uint(f);
    return (u & 0x80000000u) ? ~u : (u | 0x80000000u);
}
__device__ __forceinline__ float fdec(unsigned k) {
    return (k & 0x80000000u) ? __uint_as_float(k ^ 0x80000000u) : __uint_as_float(~k);
}
#define ENC_NEG_INF 0x007FFFFFu   // fenc(-inf)

// ---------------- bucket scatter: one pass, no deg/scan ----------------
__global__ void bucket_kernel(const int* __restrict__ src, const int* __restrict__ dst,
                              const int* __restrict__ wid) {
    int i = blockIdx.x * blockDim.x + threadIdx.x;
    if (i < N_EDGES) {
        int sv = src[i];
        int d = dst[i];
        int pos = atomicAdd(&g_cur[d], 1);
        if (pos < BCAP) {   // structurally impossible to overflow for this degree dist
            g_bn[(size_t)d * BCAP + pos] = sv;
            g_bw[(size_t)d * BCAP + pos] = __ldg(&wid[sv]);
        }
    }
}

// ---------------- tensor-core GEMM (mma.sync bf16) + el/er ----------------
// Fout = tf32(X) @ tf32(W) via bf16 hi/lo split: AhBh + AlBh + AhBl (AlBl ~2^-16, dropped).
#define KP 264
#define TC_A_OFF   0
#define TC_B_OFF   (128 * KP * 2)
#define TC_EXTRA   (2 * 128 * KP * 2)
#define TC_AL_OFF  (TC_EXTRA)
#define TC_AR_OFF  (TC_EXTRA + 512)
#define TC_SMEM    (TC_EXTRA + 1024)

__global__ __launch_bounds__(256, 1) void gemm_tc_kernel(
    const float* __restrict__ X, int nrows, const float* __restrict__ W,
    const float* __restrict__ al, const float* __restrict__ ar,
    float* __restrict__ Fout, float* __restrict__ elOut, float* __restrict__ erOut)
{
    extern __shared__ char smem[];
    __nv_bfloat16* As = (__nv_bfloat16*)(smem + TC_A_OFF);
    __nv_bfloat16* Bs = (__nv_bfloat16*)(smem + TC_B_OFF);
    float* als = (float*)(smem + TC_AL_OFF);
    float* ars = (float*)(smem + TC_AR_OFF);
    float* Ds  = (float*)(smem + TC_A_OFF);        // overlays As/Bs after MMA

    int t = threadIdx.x, wid = t >> 5, lane = t & 31;
    int g = lane >> 2, tq = lane & 3;
    int wm = wid >> 1, wn = wid & 1;
    int row0 = blockIdx.x * 128;

    if (t < 128) { als[t] = al[t]; ars[t] = ar[t]; }

    // ---- load A rows (hi/lo split): 2 threads per row ----
    {
        int r = t >> 1, kh = t & 1;
        bool valid = (row0 + r) < nrows;
        const float* xr = X ? (X + (size_t)(row0 + r) * 128) : (g_h + (size_t)(row0 + r) * 128);
        __nv_bfloat16* ah = As + r * KP + kh * 64;
        __nv_bfloat16* av = ah + 128;
#pragma unroll
        for (int f = 0; f < 16; f++) {
            float4 v = make_float4(0.f, 0.f, 0.f, 0.f);
            if (valid) v = ((const float4*)xr)[kh * 16 + f];
            __nv_bfloat16 h0, h1, h2, h3, l0, l1, l2, l3;
            split_bf(v.x, h0, l0); split_bf(v.y, h1, l1);
            split_bf(v.z, h2, l2); split_bf(v.w, h3, l3);
            ((__nv_bfloat162*)(ah + f * 4))[0] = __halves2bfloat162(h0, h1);
            ((__nv_bfloat162*)(ah + f * 4))[1] = __halves2bfloat162(h2, h3);
            ((__nv_bfloat162*)(av + f * 4))[0] = __halves2bfloat162(l0, l1);
            ((__nv_bfloat162*)(av + f * 4))[1] = __halves2bfloat162(l2, l3);
        }
    }
    // ---- load B = W^T (hi/lo): Bs[n][k]; 2 threads per W row k ----
    {
        int k = t >> 1, nh = t & 1;
#pragma unroll 4
        for (int j = 0; j < 16; j++) {
            float4 v = ((const float4*)(W + (size_t)k * 128 + nh * 64))[j];
            float vv[4] = {v.x, v.y, v.z, v.w};
#pragma unroll
            for (int e = 0; e < 4; e++) {
                int n = nh * 64 + j * 4 + e;
                __nv_bfloat16 hh, ll;
                split_bf(vv[e], hh, ll);
                Bs[n * KP + k]       = hh;
                Bs[n * KP + 128 + k] = ll;
            }
        }
    }
    __syncthreads();

    float acc[2][8][4];
#pragma unroll
    for (int mt = 0; mt < 2; mt++)
#pragma unroll
        for (int nt = 0; nt < 8; nt++)
#pragma unroll
            for (int c = 0; c < 4; c++) acc[mt][nt][c] = 0.f;

#pragma unroll
    for (int s = 0; s < 24; s++) {
        int abase = (s < 8) ? s * 16 : (s < 16) ? 128 + (s - 8) * 16 : (s - 16) * 16;
        int bbase = (s < 8) ? s * 16 : (s < 16) ? (s - 8) * 16 : 128 + (s - 16) * 16;
        uint32_t af[2][4], bf[8][2];
#pragma unroll
        for (int mt = 0; mt < 2; mt++) {
            int r = wm * 32 + mt * 16 + g;
            af[mt][0] = *(const uint32_t*)&As[r * KP + abase + 2 * tq];
            af[mt][1] = *(const uint32_t*)&As[(r + 8) * KP + abase + 2 * tq];
            af[mt][2] = *(const uint32_t*)&As[r * KP + abase + 2 * tq + 8];
            af[mt][3] = *(const uint32_t*)&As[(r + 8) * KP + abase + 2 * tq + 8];
        }
#pragma unroll
        for (int nt = 0; nt < 8; nt++) {
            int n = wn * 64 + nt * 8 + g;
            bf[nt][0] = *(const uint32_t*)&Bs[n * KP + bbase + 2 * tq];
            bf[nt][1] = *(const uint32_t*)&Bs[n * KP + bbase + 2 * tq + 8];
        }
#pragma unroll
        for (int mt = 0; mt < 2; mt++)
#pragma unroll
            for (int nt = 0; nt < 8; nt++)
                asm volatile(
                    "mma.sync.aligned.m16n8k16.row.col.f32.bf16.bf16.f32 "
                    "{%0,%1,%2,%3}, {%4,%5,%6,%7}, {%8,%9}, {%0,%1,%2,%3};"
                    : "+f"(acc[mt][nt][0]), "+f"(acc[mt][nt][1]),
                      "+f"(acc[mt][nt][2]), "+f"(acc[mt][nt][3])
                    : "r"(af[mt][0]), "r"(af[mt][1]), "r"(af[mt][2]), "r"(af[mt][3]),
                      "r"(bf[nt][0]), "r"(bf[nt][1]));
    }
    __syncthreads();   // all warps done reading As/Bs

    // ---- stage C to Ds[128][132] (overlays As/Bs) ----
#pragma unroll
    for (int mt = 0; mt < 2; mt++)
#pragma unroll
        for (int nt = 0; nt < 8; nt++) {
            int r = wm * 32 + mt * 16 + g;
            int c = wn * 64 + nt * 8 + 2 * tq;
            *(float2*)&Ds[r * 132 + c]       = make_float2(acc[mt][nt][0], acc[mt][nt][1]);
            *(float2*)&Ds[(r + 8) * 132 + c] = make_float2(acc[mt][nt][2], acc[mt][nt][3]);
        }
    __syncthreads();

    // ---- el/er from staged C ----
    if (wid < 4) {
        int rr = wid * 32 + lane;
        int node = row0 + rr;
        if (node < nrows) {
#pragma unroll
            for (int h = 0; h < 4; h++) {
                float sa = 0.f, sb = 0.f;
#pragma unroll
                for (int d = 0; d < 32; d++) {
                    float fv = Ds[rr * 132 + h * 32 + d];
                    sa += fv * als[h * 32 + d];
                    sb += fv * ars[h * 32 + d];
                }
                elOut[node * HEADS + h] = sa;
                erOut[node * HEADS + h] = sb;
            }
        }
    }

    // ---- feat writeback: head-interleaved float4 rows, coalesced ----
#pragma unroll 4
    for (int it = 0; it < 16; it++) {
        int rr = wid * 16 + it;
        int node = row0 + rr;
        if (node < nrows) {
            float4 o;
            o.x = Ds[rr * 132 +      lane];
            o.y = Ds[rr * 132 + 32 + lane];
            o.z = Ds[rr * 132 + 64 + lane];
            o.w = Ds[rr * 132 + 96 + lane];
            ((float4*)(Fout + (size_t)node * 128))[lane] = o;   // frow[d*4+h]
        }
    }
}

// ---------------- edge-parallel attention coefficients ----------------
// One thread per bucket slot: p[slot][h] = exp(leaky(el[src]+er[dst])).
__global__ void attn_kernel(const float* __restrict__ ELV, const float* __restrict__ ERV,
                            const int* __restrict__ dstmap, const int* __restrict__ srcb) {
    int idx = blockIdx.x * blockDim.x + threadIdx.x;
    if (idx >= N_NODES * BCAP) return;
    int n = idx >> 6;                  // BCAP = 64
    int slot = idx & (BCAP - 1);
    int deg = __ldg(&g_cur[n]); if (deg > BCAP) deg = BCAP;
    if (slot >= deg) return;
    int r = __ldg(&srcb[idx]);
    float4 el4 = *(const float4*)&ELV[r * HEADS];
    int nr = dstmap ? __ldg(&dstmap[n]) : n;
    float4 er4 = *(const float4*)&ERV[nr * HEADS];
    float4 p;
    float x0 = el4.x + er4.x; p.x = __expf(fmaxf(x0, NEG_SLOPE * x0));
    float x1 = el4.y + er4.y; p.y = __expf(fmaxf(x1, NEG_SLOPE * x1));
    float x2 = el4.z + er4.z; p.z = __expf(fmaxf(x2, NEG_SLOPE * x2));
    float x3 = el4.w + er4.w; p.w = __expf(fmaxf(x3, NEG_SLOPE * x3));
    g_bp[idx] = p;
}

// ---------------- edge aggregation: TWO warps per dst node ----------------
// Warp pair (half=0/1) processes even/odd bucket slots; partials combined in
// shared memory. Halves the serial chain and doubles latency-hiding warps.
// Named prefetch registers only (no dynamic indexing -> no local-mem spill).
// 50000 nodes = 12500 blocks x 4 nodes exactly -> no partial-block sync issues.
__global__ void edge_agg_kernel(const float* __restrict__ F, const int* __restrict__ srcb,
                                int reset) {
    __shared__ float4 sAcc[4][2][32];
    __shared__ float4 sDen[4][2];
    int tg = blockIdx.x * blockDim.x + threadIdx.x;
    if (reset && tg < N_GRAPHS * FEAT) g_pool[tg] = ENC_NEG_INF;   // pool runs after this kernel

    int n    = tg >> 6;          // node (2 warps per node)
    int half = (tg >> 5) & 1;    // which warp of the pair
    int lane = tg & 31;
    int nb   = threadIdx.x >> 6; // node slot within block (0..3)

    float den[4] = {0.f, 0.f, 0.f, 0.f};
    float acc[4] = {0.f, 0.f, 0.f, 0.f};

    int deg = __ldg(&g_cur[n]); if (deg > BCAP) deg = BCAP;
    const int* bk = srcb + (size_t)n * BCAP;
    const float4* bp = g_bp + (size_t)n * BCAP;

    // this warp handles slots half, half+2, half+4, ...
    float4 p_p  = make_float4(0.f, 0.f, 0.f, 0.f);
    float4 fv_p = make_float4(0.f, 0.f, 0.f, 0.f);
    int i = half;
    if (i < deg) {
        int r = __ldg(&bk[i]);
        p_p  = __ldg(&bp[i]);                                        // warp-broadcast
        fv_p = __ldg((const float4*)(F + (size_t)r * FEAT) + lane);  // [h0..h3] for dim=lane
    }
    for (; i < deg; i += 2) {
        float4 p4  = p_p;
        float4 fv4 = fv_p;
        if (i + 2 < deg) {
            int r = __ldg(&bk[i + 2]);
            p_p  = __ldg(&bp[i + 2]);
            fv_p = __ldg((const float4*)(F + (size_t)r * FEAT) + lane);
        }
        den[0] += p4.x; acc[0] += p4.x * fv4.x;
        den[1] += p4.y; acc[1] += p4.y * fv4.y;
        den[2] += p4.z; acc[2] += p4.z * fv4.z;
        den[3] += p4.w; acc[3] += p4.w * fv4.w;
    }
    sAcc[nb][half][lane] = make_float4(acc[0], acc[1], acc[2], acc[3]);
    if (lane == 0) sDen[nb][half] = make_float4(den[0], den[1], den[2], den[3]);
    __syncthreads();

    if (half == 0) {
        float4 a0 = sAcc[nb][0][lane], a1 = sAcc[nb][1][lane];
        float4 d0 = sDen[nb][0],       d1 = sDen[nb][1];
        float dd[4] = {d0.x + d1.x, d0.y + d1.y, d0.z + d1.z, d0.w + d1.w};
        float aa[4] = {a0.x + a1.x, a0.y + a1.y, a0.z + a1.z, a0.w + a1.w};
#pragma unroll
        for (int h = 0; h < 4; h++) {
            float o = aa[h] / (dd[h] + 1e-10f);   // empty node -> 0, matches reference
            o = (o > 0.f) ? o : expm1f(o);        // elu
            g_h[(size_t)n * FEAT + h * 32 + lane] = o;
        }
        if (reset && lane == 0) g_cur[n] = 0;     // state restore for next invocation
    }
}

// ---------------- per-graph max pool ----------------
#define POOL_CHUNK 128
__global__ void pool_kernel(const int* __restrict__ gid) {
    int f = threadIdx.x;
    int n0 = blockIdx.x * POOL_CHUNK;
    int n1 = n0 + POOL_CHUNK; if (n1 > N_NODES) n1 = N_NODES;
    int cur = -1;
    unsigned best = 0;
    for (int n = n0; n < n1; n++) {
        int g = gid[n];
        unsigned enc = fenc(g_h[(size_t)n * FEAT + f]);
        if (g != cur) {
            if (cur >= 0) atomicMax(&g_pool[cur * FEAT + f], best);
            cur = g; best = enc;
        } else {
            best = best > enc ? best : enc;
        }
    }
    if (cur >= 0) atomicMax(&g_pool[cur * FEAT + f], best);
}

// ---------------- readout ----------------
__global__ void final_kernel(const float* __restrict__ y, const float* __restrict__ ow,
                             const float* __restrict__ ob, float* __restrict__ out) {
    int g = threadIdx.x;   // 64 threads
    float s = 0.f;
    for (int k = 0; k < FEAT; k++) {
        float v = fdec(g_pool[g * FEAT + k]);
        if (!isfinite(v)) v = 0.f;
        s += tf32r(v) * tf32r(ow[k]);
    }
    float l = s + ob[0];
    out[1 + g] = 1.f / (1.f + expf(-l));
    float bce = fmaxf(l, 0.f) - l * y[g] + log1pf(expf(-fabsf(l)));
    __shared__ float sh[64];
    sh[g] = bce;
    __syncthreads();
    for (int st = 32; st > 0; st >>= 1) {
        if (g < st) sh[g] += sh[g + st];
        __syncthreads();
    }
    if (g == 0) out[0] = sh[0] / (float)N_GRAPHS;
}

extern "C" void kernel_launch(void* const* d_in, const int* in_sizes, int n_in,
                              void* d_out, int out_size) {
    const int*   word_ids   = (const int*)  d_in[0];
    const int*   edge_src   = (const int*)  d_in[1];
    const int*   edge_dst   = (const int*)  d_in[2];
    const int*   node_gid   = (const int*)  d_in[3];
    const float* y_data     = (const float*)d_in[4];
    const float* word_emb   = (const float*)d_in[5];
    const float* W0         = (const float*)d_in[6];
    const float* al0        = (const float*)d_in[7];
    const float* ar0        = (const float*)d_in[8];
    const float* W1         = (const float*)d_in[9];
    const float* al1        = (const float*)d_in[10];
    const float* ar1        = (const float*)d_in[11];
    const float* out_w      = (const float*)d_in[12];
    const float* out_b      = (const float*)d_in[13];
    float* out = (float*)d_out;

    static float *pV = nullptr, *pElv, *pErv, *pFeat, *pEl, *pEr;
    static int *pBn, *pBw;
    if (!pV) {   // resolved once; pure address lookup, enqueues no work
        cudaGetSymbolAddress((void**)&pV,    g_V);
        cudaGetSymbolAddress((void**)&pElv,  g_elv);
        cudaGetSymbolAddress((void**)&pErv,  g_erv);
        cudaGetSymbolAddress((void**)&pFeat, g_feat);
        cudaGetSymbolAddress((void**)&pEl,   g_el);
        cudaGetSymbolAddress((void**)&pEr,   g_er);
        cudaGetSymbolAddress((void**)&pBn,   g_bn);
        cudaGetSymbolAddress((void**)&pBw,   g_bw);
        cudaFuncSetAttribute(gemm_tc_kernel, cudaFuncAttributeMaxDynamicSharedMemorySize, TC_SMEM);
    }

    int agg_blocks  = (N_NODES * 64) / 256;              // 2 warps per node, exact
    int attn_blocks = (N_NODES * BCAP + 255) / 256;      // one thread per bucket slot

    // 1: bucket scatter (g_cur starts zero: static init / reset by previous agg1)
    bucket_kernel<<<(N_EDGES + 255) / 256, 256>>>(edge_src, edge_dst, word_ids);
    // 2: layer-0 GEMM over distinct vocab rows
    gemm_tc_kernel<<<(VOCAB + 127) / 128, 256, TC_SMEM>>>(
        word_emb, VOCAB, W0, al0, ar0, pV, pElv, pErv);
    // 3: layer-0 edge attention (edge-parallel)
    attn_kernel<<<attn_blocks, 256>>>(pElv, pErv, word_ids, pBw);
    // 4: layer-0 aggregation (ncu-profiled slot)
    edge_agg_kernel<<<agg_blocks, 256>>>(pV, pBw, 0);
    // 5: layer-1 GEMM
    gemm_tc_kernel<<<(N_NODES + 127) / 128, 256, TC_SMEM>>>(
        nullptr, N_NODES, W1, al1, ar1, pFeat, pEl, pEr);
    // 6: layer-1 edge attention
    attn_kernel<<<attn_blocks, 256>>>(pEl, pEr, nullptr, pBn);
    // 7: layer-1 aggregation (+ state restore: g_cur=0, pool armed)
    edge_agg_kernel<<<agg_blocks, 256>>>(pFeat, pBn, 1);
    // 8-9: pooling + readout
    pool_kernel<<<(N_NODES + POOL_CHUNK - 1) / POOL_CHUNK, 128>>>(node_gid);
    final_kernel<<<1, 64>>>(y_data, out_w, out_b, out);
}

// round 16
// speedup vs baseline: 1.2173x; 1.2173x over previous
#include <cuda_runtime.h>
#include <cuda_bf16.h>
#include <math.h>
#include <stdint.h>

#define N_NODES 50000
#define N_EDGES 800000
#define VOCAB 15000
#define IN_FEATS 128
#define HIDDEN 32
#define HEADS 4
#define FEAT 128           // HEADS*HIDDEN
#define N_GRAPHS 64
#define NEG_SLOPE 0.2f
#define BCAP 64            // bucket capacity per node (P(deg>=64) ~ 1e-20 for Poisson(16))

// ---------------- scratch (static device globals; no allocation) ----------------
// feat tables stored HEAD-INTERLEAVED: row[d*4 + h] = feat[h*32 + d]
__device__ __align__(16) float g_V[(size_t)VOCAB * FEAT];      // vocab-level layer-0 feat (interleaved)
__device__ __align__(16) float g_elv[VOCAB * HEADS];
__device__ __align__(16) float g_erv[VOCAB * HEADS];
__device__ __align__(16) float g_feat[(size_t)N_NODES * FEAT]; // layer-1 feat (interleaved)
__device__ __align__(16) float g_h[(size_t)N_NODES * FEAT];    // layer output (standard layout)
__device__ __align__(16) float g_el[N_NODES * HEADS];
__device__ __align__(16) float g_er[N_NODES * HEADS];
__device__ __align__(16) int   g_cur[N_NODES];                 // fill count; reset by agg1 (and static-init)
__device__ __align__(16) int   g_bn[(size_t)N_NODES * BCAP];   // bucket: src node ids
__device__ __align__(16) int   g_bw[(size_t)N_NODES * BCAP];   // bucket: word_ids[src]
__device__ __align__(16) float4 g_bp[(size_t)N_NODES * BCAP];  // bucket: attention exp per edge (4 heads)
__device__ unsigned g_pool[N_GRAPHS * FEAT];                   // armed by agg1 (and static zero = valid identity)

// TF32 rounding (matches JAX/XLA default f32 matmul precision on GPU)
__device__ __forceinline__ float tf32r(float x) {
    unsigned u;
    asm("cvt.rna.tf32.f32 %0, %1;" : "=r"(u) : "f"(x));
    return __uint_as_float(u);
}
// exact split: bf16_hi + bf16_lo == tf32(x)
__device__ __forceinline__ void split_bf(float x, __nv_bfloat16& h, __nv_bfloat16& l) {
    float xt = tf32r(x);
    h = __float2bfloat16(xt);
    l = __float2bfloat16(xt - __bfloat162float(h));
}

// order-preserving float <-> uint encode for atomicMax
__device__ __forceinline__ unsigned fenc(float f) {
    unsigned u = __float_as_uint(f);
    return (u & 0x80000000u) ? ~u : (u | 0x80000000u);
}
__device__ __forceinline__ float fdec(unsigned k) {
    return (k & 0x80000000u) ? __uint_as_float(k ^ 0x80000000u) : __uint_as_float(~k);
}
#define ENC_NEG_INF 0x007FFFFFu   // fenc(-inf)

// ---------------- bucket scatter: one pass, no deg/scan ----------------
__global__ void bucket_kernel(const int* __restrict__ src, const int* __restrict__ dst,
                              const int* __restrict__ wid) {
    int i = blockIdx.x * blockDim.x + threadIdx.x;
    if (i < N_EDGES) {
        int sv = src[i];
        int d = dst[i];
        int pos = atomicAdd(&g_cur[d], 1);
        if (pos < BCAP) {   // structurally impossible to overflow for this degree dist
            g_bn[(size_t)d * BCAP + pos] = sv;
            g_bw[(size_t)d * BCAP + pos] = __ldg(&wid[sv]);
        }
    }
}

// ---------------- tensor-core GEMM (mma.sync bf16) + el/er ----------------
// Fout = tf32(X) @ tf32(W) via bf16 hi/lo split: AhBh + AlBh + AhBl (AlBl ~2^-16, dropped).
#define KP 264
#define TC_A_OFF   0
#define TC_B_OFF   (128 * KP * 2)
#define TC_EXTRA   (2 * 128 * KP * 2)
#define TC_AL_OFF  (TC_EXTRA)
#define TC_AR_OFF  (TC_EXTRA + 512)
#define TC_SMEM    (TC_EXTRA + 1024)

__global__ __launch_bounds__(256, 1) void gemm_tc_kernel(
    const float* __restrict__ X, int nrows, const float* __restrict__ W,
    const float* __restrict__ al, const float* __restrict__ ar,
    float* __restrict__ Fout, float* __restrict__ elOut, float* __restrict__ erOut)
{
    extern __shared__ char smem[];
    __nv_bfloat16* As = (__nv_bfloat16*)(smem + TC_A_OFF);
    __nv_bfloat16* Bs = (__nv_bfloat16*)(smem + TC_B_OFF);
    float* als = (float*)(smem + TC_AL_OFF);
    float* ars = (float*)(smem + TC_AR_OFF);
    float* Ds  = (float*)(smem + TC_A_OFF);        // overlays As/Bs after MMA

    int t = threadIdx.x, wid = t >> 5, lane = t & 31;
    int g = lane >> 2, tq = lane & 3;
    int wm = wid >> 1, wn = wid & 1;
    int row0 = blockIdx.x * 128;

    if (t < 128) { als[t] = al[t]; ars[t] = ar[t]; }

    // ---- load A rows (hi/lo split): 2 threads per row ----
    {
        int r = t >> 1, kh = t & 1;
        bool valid = (row0 + r) < nrows;
        const float* xr = X ? (X + (size_t)(row0 + r) * 128) : (g_h + (size_t)(row0 + r) * 128);
        __nv_bfloat16* ah = As + r * KP + kh * 64;
        __nv_bfloat16* av = ah + 128;
#pragma unroll
        for (int f = 0; f < 16; f++) {
            float4 v = make_float4(0.f, 0.f, 0.f, 0.f);
            if (valid) v = ((const float4*)xr)[kh * 16 + f];
            __nv_bfloat16 h0, h1, h2, h3, l0, l1, l2, l3;
            split_bf(v.x, h0, l0); split_bf(v.y, h1, l1);
            split_bf(v.z, h2, l2); split_bf(v.w, h3, l3);
            ((__nv_bfloat162*)(ah + f * 4))[0] = __halves2bfloat162(h0, h1);
            ((__nv_bfloat162*)(ah + f * 4))[1] = __halves2bfloat162(h2, h3);
            ((__nv_bfloat162*)(av + f * 4))[0] = __halves2bfloat162(l0, l1);
            ((__nv_bfloat162*)(av + f * 4))[1] = __halves2bfloat162(l2, l3);
        }
    }
    // ---- load B = W^T (hi/lo): Bs[n][k]; 2 threads per W row k ----
    {
        int k = t >> 1, nh = t & 1;
#pragma unroll 4
        for (int j = 0; j < 16; j++) {
            float4 v = ((const float4*)(W + (size_t)k * 128 + nh * 64))[j];
            float vv[4] = {v.x, v.y, v.z, v.w};
#pragma unroll
            for (int e = 0; e < 4; e++) {
                int n = nh * 64 + j * 4 + e;
                __nv_bfloat16 hh, ll;
                split_bf(vv[e], hh, ll);
                Bs[n * KP + k]       = hh;
                Bs[n * KP + 128 + k] = ll;
            }
        }
    }
    __syncthreads();

    float acc[2][8][4];
#pragma unroll
    for (int mt = 0; mt < 2; mt++)
#pragma unroll
        for (int nt = 0; nt < 8; nt++)
#pragma unroll
            for (int c = 0; c < 4; c++) acc[mt][nt][c] = 0.f;

#pragma unroll
    for (int s = 0; s < 24; s++) {
        int abase = (s < 8) ? s * 16 : (s < 16) ? 128 + (s - 8) * 16 : (s - 16) * 16;
        int bbase = (s < 8) ? s * 16 : (s < 16) ? (s - 8) * 16 : 128 + (s - 16) * 16;
        uint32_t af[2][4], bf[8][2];
#pragma unroll
        for (int mt = 0; mt < 2; mt++) {
            int r = wm * 32 + mt * 16 + g;
            af[mt][0] = *(const uint32_t*)&As[r * KP + abase + 2 * tq];
            af[mt][1] = *(const uint32_t*)&As[(r + 8) * KP + abase + 2 * tq];
            af[mt][2] = *(const uint32_t*)&As[r * KP + abase + 2 * tq + 8];
            af[mt][3] = *(const uint32_t*)&As[(r + 8) * KP + abase + 2 * tq + 8];
        }
#pragma unroll
        for (int nt = 0; nt < 8; nt++) {
            int n = wn * 64 + nt * 8 + g;
            bf[nt][0] = *(const uint32_t*)&Bs[n * KP + bbase + 2 * tq];
            bf[nt][1] = *(const uint32_t*)&Bs[n * KP + bbase + 2 * tq + 8];
        }
#pragma unroll
        for (int mt = 0; mt < 2; mt++)
#pragma unroll
            for (int nt = 0; nt < 8; nt++)
                asm volatile(
                    "mma.sync.aligned.m16n8k16.row.col.f32.bf16.bf16.f32 "
                    "{%0,%1,%2,%3}, {%4,%5,%6,%7}, {%8,%9}, {%0,%1,%2,%3};"
                    : "+f"(acc[mt][nt][0]), "+f"(acc[mt][nt][1]),
                      "+f"(acc[mt][nt][2]), "+f"(acc[mt][nt][3])
                    : "r"(af[mt][0]), "r"(af[mt][1]), "r"(af[mt][2]), "r"(af[mt][3]),
                      "r"(bf[nt][0]), "r"(bf[nt][1]));
    }
    __syncthreads();   // all warps done reading As/Bs

    // ---- stage C to Ds[128][132] (overlays As/Bs) ----
#pragma unroll
    for (int mt = 0; mt < 2; mt++)
#pragma unroll
        for (int nt = 0; nt < 8; nt++) {
            int r = wm * 32 + mt * 16 + g;
            int c = wn * 64 + nt * 8 + 2 * tq;
            *(float2*)&Ds[r * 132 + c]       = make_float2(acc[mt][nt][0], acc[mt][nt][1]);
            *(float2*)&Ds[(r + 8) * 132 + c] = make_float2(acc[mt][nt][2], acc[mt][nt][3]);
        }
    __syncthreads();

    // ---- el/er from staged C ----
    if (wid < 4) {
        int rr = wid * 32 + lane;
        int node = row0 + rr;
        if (node < nrows) {
#pragma unroll
            for (int h = 0; h < 4; h++) {
                float sa = 0.f, sb = 0.f;
#pragma unroll
                for (int d = 0; d < 32; d++) {
                    float fv = Ds[rr * 132 + h * 32 + d];
                    sa += fv * als[h * 32 + d];
                    sb += fv * ars[h * 32 + d];
                }
                elOut[node * HEADS + h] = sa;
                erOut[node * HEADS + h] = sb;
            }
        }
    }

    // ---- feat writeback: head-interleaved float4 rows, coalesced ----
#pragma unroll 4
    for (int it = 0; it < 16; it++) {
        int rr = wid * 16 + it;
        int node = row0 + rr;
        if (node < nrows) {
            float4 o;
            o.x = Ds[rr * 132 +      lane];
            o.y = Ds[rr * 132 + 32 + lane];
            o.z = Ds[rr * 132 + 64 + lane];
            o.w = Ds[rr * 132 + 96 + lane];
            ((float4*)(Fout + (size_t)node * 128))[lane] = o;   // frow[d*4+h]
        }
    }
}

// ---------------- edge-parallel attention coefficients: one WARP per node ----------------
// Lanes sweep bucket slots (lane, lane+32): <=2 iterations at deg~16, tight
// utilization, 1.6M threads total (vs 6.4M thread-per-slot version).
__global__ void attn_kernel(const float* __restrict__ ELV, const float* __restrict__ ERV,
                            const int* __restrict__ dstmap, const int* __restrict__ srcb) {
    int gw = (blockIdx.x * blockDim.x + threadIdx.x) >> 5;
    int lane = threadIdx.x & 31;
    if (gw >= N_NODES) return;
    int n = gw;
    int deg = __ldg(&g_cur[n]); if (deg > BCAP) deg = BCAP;
    int nr = dstmap ? __ldg(&dstmap[n]) : n;
    float4 er4 = *(const float4*)&ERV[nr * HEADS];
#pragma unroll
    for (int i = lane; i < BCAP; i += 32) {
        if (i < deg) {
            int r = __ldg(&srcb[(size_t)n * BCAP + i]);
            float4 el4 = *(const float4*)&ELV[r * HEADS];
            float4 p;
            float x0 = el4.x + er4.x; p.x = __expf(fmaxf(x0, NEG_SLOPE * x0));
            float x1 = el4.y + er4.y; p.y = __expf(fmaxf(x1, NEG_SLOPE * x1));
            float x2 = el4.z + er4.z; p.z = __expf(fmaxf(x2, NEG_SLOPE * x2));
            float x3 = el4.w + er4.w; p.w = __expf(fmaxf(x3, NEG_SLOPE * x3));
            g_bp[(size_t)n * BCAP + i] = p;
        }
    }
}

// ---------------- edge aggregation: one warp per dst node (R14 version) ----------------
// Slim loop: per edge {src id, p (broadcast), fv gather, den+=p, acc+=p*fv}.
// Named prefetch registers (no dynamic indexing -> no local-mem spill).
// reset!=0 (layer 1): also resets g_cur and re-arms g_pool for next invocation.
__global__ void edge_agg_kernel(const float* __restrict__ F, const int* __restrict__ srcb,
                                int reset) {
    int tg = blockIdx.x * blockDim.x + threadIdx.x;
    if (reset && tg < N_GRAPHS * FEAT) g_pool[tg] = ENC_NEG_INF;   // pool runs after this kernel

    int gw = tg >> 5;
    int lane = tg & 31;
    if (gw >= N_NODES) return;
    int n = gw;

    float den[4] = {0.f, 0.f, 0.f, 0.f};
    float acc[4] = {0.f, 0.f, 0.f, 0.f};

    int deg = __ldg(&g_cur[n]); if (deg > BCAP) deg = BCAP;
    const int* bk = srcb + (size_t)n * BCAP;
    const float4* bp = g_bp + (size_t)n * BCAP;

    float4 p_p  = make_float4(0.f, 0.f, 0.f, 0.f);
    float4 fv_p = make_float4(0.f, 0.f, 0.f, 0.f);
    if (deg > 0) {
        int r = __ldg(&bk[0]);
        p_p  = __ldg(&bp[0]);                                        // warp-broadcast
        fv_p = __ldg((const float4*)(F + (size_t)r * FEAT) + lane);  // [h0,h1,h2,h3] for dim=lane
    }
    for (int i = 0; i < deg; i++) {
        float4 p4  = p_p;
        float4 fv4 = fv_p;
        if (i + 1 < deg) {
            int r = __ldg(&bk[i + 1]);
            p_p  = __ldg(&bp[i + 1]);
            fv_p = __ldg((const float4*)(F + (size_t)r * FEAT) + lane);
        }
        den[0] += p4.x; acc[0] += p4.x * fv4.x;
        den[1] += p4.y; acc[1] += p4.y * fv4.y;
        den[2] += p4.z; acc[2] += p4.z * fv4.z;
        den[3] += p4.w; acc[3] += p4.w * fv4.w;
    }
#pragma unroll
    for (int h = 0; h < 4; h++) {
        float o = acc[h] / (den[h] + 1e-10f);  // empty node -> 0, matches reference
        o = (o > 0.f) ? o : expm1f(o);         // elu
        g_h[(size_t)n * FEAT + h * 32 + lane] = o;
    }
    if (reset && lane == 0) g_cur[n] = 0;      // state restore for next invocation
}

// ---------------- per-graph max pool ----------------
#define POOL_CHUNK 128
__global__ void pool_kernel(const int* __restrict__ gid) {
    int f = threadIdx.x;
    int n0 = blockIdx.x * POOL_CHUNK;
    int n1 = n0 + POOL_CHUNK; if (n1 > N_NODES) n1 = N_NODES;
    int cur = -1;
    unsigned best = 0;
    for (int n = n0; n < n1; n++) {
        int g = gid[n];
        unsigned enc = fenc(g_h[(size_t)n * FEAT + f]);
        if (g != cur) {
            if (cur >= 0) atomicMax(&g_pool[cur * FEAT + f], best);
            cur = g; best = enc;
        } else {
            best = best > enc ? best : enc;
        }
    }
    if (cur >= 0) atomicMax(&g_pool[cur * FEAT + f], best);
}

// ---------------- readout ----------------
__global__ void final_kernel(const float* __restrict__ y, const float* __restrict__ ow,
                             const float* __restrict__ ob, float* __restrict__ out) {
    int g = threadIdx.x;   // 64 threads
    float s = 0.f;
    for (int k = 0; k < FEAT; k++) {
        float v = fdec(g_pool[g * FEAT + k]);
        if (!isfinite(v)) v = 0.f;
        s += tf32r(v) * tf32r(ow[k]);
    }
    float l = s + ob[0];
    out[1 + g] = 1.f / (1.f + expf(-l));
    float bce = fmaxf(l, 0.f) - l * y[g] + log1pf(expf(-fabsf(l)));
    __shared__ float sh[64];
    sh[g] = bce;
    __syncthreads();
    for (int st = 32; st > 0; st >>= 1) {
        if (g < st) sh[g] += sh[g + st];
        __syncthreads();
    }
    if (g == 0) out[0] = sh[0] / (float)N_GRAPHS;
}

extern "C" void kernel_launch(void* const* d_in, const int* in_sizes, int n_in,
                              void* d_out, int out_size) {
    const int*   word_ids   = (const int*)  d_in[0];
    const int*   edge_src   = (const int*)  d_in[1];
    const int*   edge_dst   = (const int*)  d_in[2];
    const int*   node_gid   = (const int*)  d_in[3];
    const float* y_data     = (const float*)d_in[4];
    const float* word_emb   = (const float*)d_in[5];
    const float* W0         = (const float*)d_in[6];
    const float* al0        = (const float*)d_in[7];
    const float* ar0        = (const float*)d_in[8];
    const float* W1         = (const float*)d_in[9];
    const float* al1        = (const float*)d_in[10];
    const float* ar1        = (const float*)d_in[11];
    const float* out_w      = (const float*)d_in[12];
    const float* out_b      = (const float*)d_in[13];
    float* out = (float*)d_out;

    static float *pV = nullptr, *pElv, *pErv, *pFeat, *pEl, *pEr;
    static int *pBn, *pBw;
    if (!pV) {   // resolved once; pure address lookup, enqueues no work
        cudaGetSymbolAddress((void**)&pV,    g_V);
        cudaGetSymbolAddress((void**)&pElv,  g_elv);
        cudaGetSymbolAddress((void**)&pErv,  g_erv);
        cudaGetSymbolAddress((void**)&pFeat, g_feat);
        cudaGetSymbolAddress((void**)&pEl,   g_el);
        cudaGetSymbolAddress((void**)&pEr,   g_er);
        cudaGetSymbolAddress((void**)&pBn,   g_bn);
        cudaGetSymbolAddress((void**)&pBw,   g_bw);
        cudaFuncSetAttribute(gemm_tc_kernel, cudaFuncAttributeMaxDynamicSharedMemorySize, TC_SMEM);
    }

    int agg_blocks  = (N_NODES * 32 + 255) / 256;        // one warp per node
    int attn_blocks = agg_blocks;                        // one warp per node

    // 1: bucket scatter (g_cur starts zero: static init / reset by previous agg1)
    bucket_kernel<<<(N_EDGES + 255) / 256, 256>>>(edge_src, edge_dst, word_ids);
    // 2: layer-0 GEMM over distinct vocab rows
    gemm_tc_kernel<<<(VOCAB + 127) / 128, 256, TC_SMEM>>>(
        word_emb, VOCAB, W0, al0, ar0, pV, pElv, pErv);
    // 3: layer-0 edge attention (warp-per-node)
    attn_kernel<<<attn_blocks, 256>>>(pElv, pErv, word_ids, pBw);
    // 4: layer-0 aggregation (ncu-profiled slot)
    edge_agg_kernel<<<agg_blocks, 256>>>(pV, pBw, 0);
    // 5: layer-1 GEMM
    gemm_tc_kernel<<<(N_NODES + 127) / 128, 256, TC_SMEM>>>(
        nullptr, N_NODES, W1, al1, ar1, pFeat, pEl, pEr);
    // 6: layer-1 edge attention
    attn_kernel<<<attn_blocks, 256>>>(pEl, pEr, nullptr, pBn);
    // 7: layer-1 aggregation (+ state restore: g_cur=0, pool armed)
    edge_agg_kernel<<<agg_blocks, 256>>>(pFeat, pBn, 1);
    // 8-9: pooling + readout
    pool_kernel<<<(N_NODES + POOL_CHUNK - 1) / POOL_CHUNK, 128>>>(node_gid);
    final_kernel<<<1, 64>>>(y_data, out_w, out_b, out);
}